// round 1
// baseline (speedup 1.0000x reference)
#include <cuda_runtime.h>

#define NN   50000
#define EE   1600000
#define HIDD 128

// ---------------- scratch (static device globals; no runtime allocation) ----
__device__ __align__(256) float g_buf0[(size_t)NN * HIDD];
__device__ __align__(256) float g_buf1[(size_t)NN * HIDD];
__device__ __align__(256) float g_buf2[(size_t)NN * HIDD];
__device__ int g_deg[NN];
__device__ int g_rowptr[NN + 1];
__device__ int g_pos[NN];
__device__ int g_col[EE];
__device__ __align__(16) float g_sum[HIDD];
__device__ __align__(16) float g_ss[HIDD];
__device__ __align__(16) float g_scale[HIDD];
__device__ __align__(16) float g_shift[HIDD];

// ---------------- f32x2 packed-FMA helpers (2 FMAs per issue slot) ----------
__device__ __forceinline__ unsigned long long fma2(unsigned long long a,
                                                   unsigned long long b,
                                                   unsigned long long c) {
    unsigned long long d;
    asm("fma.rn.f32x2 %0, %1, %2, %3;" : "=l"(d) : "l"(a), "l"(b), "l"(c));
    return d;
}
__device__ __forceinline__ unsigned long long pk2(float lo, float hi) {
    unsigned long long d;
    asm("mov.b64 %0, {%1, %2};" : "=l"(d) : "f"(lo), "f"(hi));
    return d;
}
__device__ __forceinline__ float2 upk2(unsigned long long v) {
    float2 r;
    asm("mov.b64 {%0, %1}, %2;" : "=f"(r.x), "=f"(r.y) : "l"(v));
    return r;
}

// ---------------- GEMM: C[M,128] = sum_parts A_p[M,K] @ W_p[K,128] + bias ---
// BM=128, BN=128 (full), BK=16, 256 threads, 8x8 micro-tile per thread.
__global__ void __launch_bounds__(256, 2) gemm_kernel(
    const float* __restrict__ A1, const float* __restrict__ W1,
    const float* __restrict__ A2, const float* __restrict__ W2,
    const float* __restrict__ bias, float* __restrict__ C,
    int M, int K, int nparts)
{
    __shared__ float As[16][128];
    __shared__ float Bs[16][128];
    const int tid = threadIdx.x;
    const int tx = tid & 15;   // col group
    const int ty = tid >> 4;   // row group
    const int m0 = blockIdx.x * 128;

    unsigned long long acc[8][4];
#pragma unroll
    for (int i = 0; i < 8; i++)
#pragma unroll
        for (int j = 0; j < 4; j++) acc[i][j] = 0ULL;

    for (int part = 0; part < nparts; ++part) {
        const float* A = part ? A2 : A1;
        const float* W = part ? W2 : W1;
        for (int kk = 0; kk < K; kk += 16) {
            // A tile: 128 rows x 16 k (store transposed into As[k][row])
#pragma unroll
            for (int l = 0; l < 2; l++) {
                int f = tid + l * 256;
                int row = f >> 2;
                int kp = (f & 3) << 2;
                int grow = m0 + row;
                float4 v = make_float4(0.f, 0.f, 0.f, 0.f);
                if (grow < M)
                    v = __ldg((const float4*)(A + (size_t)grow * K + kk + kp));
                As[kp + 0][row] = v.x; As[kp + 1][row] = v.y;
                As[kp + 2][row] = v.z; As[kp + 3][row] = v.w;
            }
            // B tile: 16 k-rows x 128 cols
#pragma unroll
            for (int l = 0; l < 2; l++) {
                int f = tid + l * 256;
                int row = f >> 5;
                int c = (f & 31) << 2;
                float4 v = __ldg((const float4*)(W + (size_t)(kk + row) * 128 + c));
                *(float4*)&Bs[row][c] = v;
            }
            __syncthreads();
#pragma unroll
            for (int k = 0; k < 16; k++) {
                float4 a0 = *(const float4*)&As[k][ty * 8];
                float4 a1 = *(const float4*)&As[k][ty * 8 + 4];
                float4 b0 = *(const float4*)&Bs[k][tx * 8];
                float4 b1 = *(const float4*)&Bs[k][tx * 8 + 4];
                unsigned long long bp0 = pk2(b0.x, b0.y);
                unsigned long long bp1 = pk2(b0.z, b0.w);
                unsigned long long bp2 = pk2(b1.x, b1.y);
                unsigned long long bp3 = pk2(b1.z, b1.w);
                float av[8] = {a0.x, a0.y, a0.z, a0.w, a1.x, a1.y, a1.z, a1.w};
#pragma unroll
                for (int i = 0; i < 8; i++) {
                    unsigned long long aa = pk2(av[i], av[i]);
                    acc[i][0] = fma2(aa, bp0, acc[i][0]);
                    acc[i][1] = fma2(aa, bp1, acc[i][1]);
                    acc[i][2] = fma2(aa, bp2, acc[i][2]);
                    acc[i][3] = fma2(aa, bp3, acc[i][3]);
                }
            }
            __syncthreads();
        }
    }
    float4 bv0 = __ldg((const float4*)(bias + tx * 8));
    float4 bv1 = __ldg((const float4*)(bias + tx * 8 + 4));
#pragma unroll
    for (int i = 0; i < 8; i++) {
        int grow = m0 + ty * 8 + i;
        if (grow >= M) continue;
        float2 p0 = upk2(acc[i][0]), p1 = upk2(acc[i][1]);
        float2 p2 = upk2(acc[i][2]), p3 = upk2(acc[i][3]);
        float4 r0 = make_float4(p0.x + bv0.x, p0.y + bv0.y, p1.x + bv0.z, p1.y + bv0.w);
        float4 r1 = make_float4(p2.x + bv1.x, p2.y + bv1.y, p3.x + bv1.z, p3.y + bv1.w);
        float4* cp = (float4*)(C + (size_t)grow * 128 + tx * 8);
        cp[0] = r0;
        cp[1] = r1;
    }
}

// ---------------- BatchNorm pipeline ----------------------------------------
__global__ void bn_zero() {
    int t = threadIdx.x;
    g_sum[t] = 0.f;
    g_ss[t] = 0.f;
}

__global__ void colstats(const float* __restrict__ X, int M) {
    int c = threadIdx.x;  // 128 threads, one column each
    float s = 0.f, ss = 0.f;
    for (int r = blockIdx.x; r < M; r += gridDim.x) {
        float v = X[(size_t)r * 128 + c];
        s += v;
        ss += v * v;
    }
    atomicAdd(&g_sum[c], s);
    atomicAdd(&g_ss[c], ss);
}

__global__ void bn_finalize(const float* __restrict__ g,
                            const float* __restrict__ be, float invM) {
    int c = threadIdx.x;
    float mean = g_sum[c] * invM;
    float var = fmaf(-mean, mean, g_ss[c] * invM);
    float r = rsqrtf(var + 1e-5f);
    float sc = g[c] * r;
    g_scale[c] = sc;
    g_shift[c] = be[c] - mean * sc;
}

template <bool RELU>
__global__ void bn_apply(const float4* __restrict__ X, float4* __restrict__ Y,
                         int n4) {
    int i = blockIdx.x * blockDim.x + threadIdx.x;
    if (i >= n4) return;
    int gsel = i & 31;  // 32 float4 per 128-col row
    float4 sc = __ldg((const float4*)g_scale + gsel);
    float4 sh = __ldg((const float4*)g_shift + gsel);
    float4 v = X[i];
    float4 r;
    r.x = fmaf(v.x, sc.x, sh.x);
    r.y = fmaf(v.y, sc.y, sh.y);
    r.z = fmaf(v.z, sc.z, sh.z);
    r.w = fmaf(v.w, sc.w, sh.w);
    if (RELU) {
        r.x = fmaxf(r.x, 0.f);
        r.y = fmaxf(r.y, 0.f);
        r.z = fmaxf(r.z, 0.f);
        r.w = fmaxf(r.w, 0.f);
    }
    Y[i] = r;
}

// ---------------- CSR build (by destination) --------------------------------
__global__ void zero_deg() {
    int i = blockIdx.x * blockDim.x + threadIdx.x;
    if (i < NN) g_deg[i] = 0;
}

__global__ void count_deg(const int* __restrict__ dst) {
    for (int e = blockIdx.x * blockDim.x + threadIdx.x; e < EE;
         e += gridDim.x * blockDim.x)
        atomicAdd(&g_deg[__ldg(&dst[e])], 1);
}

__global__ void scan_deg() {
    __shared__ int wsum[32];
    int tid = threadIdx.x, lane = tid & 31, wid = tid >> 5;
    const int CH = (NN + 1023) >> 10;  // 49
    int start = tid * CH;
    int s = 0;
    for (int i = 0; i < CH; i++) {
        int idx = start + i;
        if (idx < NN) s += g_deg[idx];
    }
    int v = s;
#pragma unroll
    for (int off = 1; off < 32; off <<= 1) {
        int t = __shfl_up_sync(0xffffffffu, v, off);
        if (lane >= off) v += t;
    }
    if (lane == 31) wsum[wid] = v;
    __syncthreads();
    if (wid == 0) {
        int w = wsum[lane];
#pragma unroll
        for (int off = 1; off < 32; off <<= 1) {
            int t = __shfl_up_sync(0xffffffffu, w, off);
            if (lane >= off) w += t;
        }
        wsum[lane] = w;
    }
    __syncthreads();
    int run = (wid ? wsum[wid - 1] : 0) + (v - s);  // exclusive prefix
    for (int i = 0; i < CH; i++) {
        int idx = start + i;
        if (idx < NN) {
            g_rowptr[idx] = run;
            g_pos[idx] = run;
            run += g_deg[idx];
        }
    }
    if (tid == 1023) g_rowptr[NN] = run;  // == total E
}

__global__ void fill_csr(const int* __restrict__ src, const int* __restrict__ dst) {
    for (int e = blockIdx.x * blockDim.x + threadIdx.x; e < EE;
         e += gridDim.x * blockDim.x) {
        int d = __ldg(&dst[e]);
        int p = atomicAdd(&g_pos[d], 1);
        g_col[p] = __ldg(&src[e]);
    }
}

// ---------------- SAGE mean aggregation: one warp per node ------------------
__global__ void sage_agg(const float4* __restrict__ feat, float4* __restrict__ outm) {
    int gw = (blockIdx.x * blockDim.x + threadIdx.x) >> 5;
    int lane = threadIdx.x & 31;
    if (gw >= NN) return;
    int beg = g_rowptr[gw], end = g_rowptr[gw + 1];
    float4 acc = make_float4(0.f, 0.f, 0.f, 0.f);
#pragma unroll 4
    for (int e = beg; e < end; e++) {
        int s = __ldg(&g_col[e]);
        float4 v = __ldg(&feat[(size_t)s * 32 + lane]);
        acc.x += v.x; acc.y += v.y; acc.z += v.z; acc.w += v.w;
    }
    int d = end - beg;
    float inv = 1.0f / (float)(d > 0 ? d : 1);
    acc.x *= inv; acc.y *= inv; acc.z *= inv; acc.w *= inv;
    outm[(size_t)gw * 32 + lane] = acc;
}

// ---------------- launch -----------------------------------------------------
extern "C" void kernel_launch(void* const* d_in, const int* in_sizes, int n_in,
                              void* d_out, int out_size) {
    const float* x     = (const float*)d_in[0];
    const int*   ei    = (const int*)d_in[1];
    const float* W_in  = (const float*)d_in[2];
    const float* b_in  = (const float*)d_in[3];
    const float* g1    = (const float*)d_in[4];
    const float* be1   = (const float*)d_in[5];
    const float* W_hid = (const float*)d_in[6];
    const float* b_hid = (const float*)d_in[7];
    const float* g2    = (const float*)d_in[8];
    const float* be2   = (const float*)d_in[9];
    const float* Wl1   = (const float*)d_in[10];
    const float* bl1   = (const float*)d_in[11];
    const float* Wr1   = (const float*)d_in[12];
    const float* g3    = (const float*)d_in[13];
    const float* be3   = (const float*)d_in[14];
    const float* Wl2   = (const float*)d_in[15];
    const float* bl2   = (const float*)d_in[16];
    const float* Wr2   = (const float*)d_in[17];
    const float* g4    = (const float*)d_in[18];
    const float* be4   = (const float*)d_in[19];

    const int M = NN;
    const int* src = ei;        // edge_index row 0
    const int* dst = ei + EE;   // edge_index row 1
    float* out_feat = (float*)d_out;
    float* out_out  = out_feat + (size_t)M * 128;

    void *pb0, *pb1, *pb2;
    cudaGetSymbolAddress(&pb0, g_buf0);
    cudaGetSymbolAddress(&pb1, g_buf1);
    cudaGetSymbolAddress(&pb2, g_buf2);
    float* b0 = (float*)pb0;
    float* b1 = (float*)pb1;
    float* b2 = (float*)pb2;

    const int n4 = M * 32;
    const int gBN = (n4 + 255) / 256;
    const int gG = (M + 127) / 128;
    const float invM = 1.0f / (float)M;

    // ---- CSR build (shared by both SAGE layers) ----
    zero_deg<<<(NN + 255) / 256, 256>>>();
    count_deg<<<4096, 256>>>(dst);
    scan_deg<<<1, 1024>>>();
    fill_csr<<<4096, 256>>>(src, dst);

    // ---- layer 1: relu(BN(x @ W_in + b_in)) ----
    gemm_kernel<<<gG, 256>>>(x, W_in, nullptr, nullptr, b_in, b0, M, 256, 1);
    bn_zero<<<1, 128>>>();
    colstats<<<512, 128>>>(b0, M);
    bn_finalize<<<1, 128>>>(g1, be1, invM);
    bn_apply<true><<<gBN, 256>>>((const float4*)b0, (float4*)b0, n4);

    // ---- layer 2: feat = relu(BN(h @ W_hid + b_hid))  -> d_out[0:N*128) ----
    gemm_kernel<<<gG, 256>>>(b0, W_hid, nullptr, nullptr, b_hid, b1, M, 128, 1);
    bn_zero<<<1, 128>>>();
    colstats<<<512, 128>>>(b1, M);
    bn_finalize<<<1, 128>>>(g2, be2, invM);
    bn_apply<true><<<gBN, 256>>>((const float4*)b1, (float4*)out_feat, n4);

    // ---- SAGE 1: BN(mean_agg(feat) @ Wl1 + bl1 + feat @ Wr1) ----
    sage_agg<<<(M * 32 + 255) / 256, 256>>>((const float4*)out_feat, (float4*)b0);
    gemm_kernel<<<gG, 256>>>(b0, Wl1, out_feat, Wr1, bl1, b1, M, 128, 2);
    bn_zero<<<1, 128>>>();
    colstats<<<512, 128>>>(b1, M);
    bn_finalize<<<1, 128>>>(g3, be3, invM);
    bn_apply<false><<<gBN, 256>>>((const float4*)b1, (float4*)b1, n4);

    // ---- SAGE 2: out = BN(mean_agg(o1) @ Wl2 + bl2 + o1 @ Wr2) -> d_out[N*128:) ----
    sage_agg<<<(M * 32 + 255) / 256, 256>>>((const float4*)b1, (float4*)b0);
    gemm_kernel<<<gG, 256>>>(b0, Wl2, b1, Wr2, bl2, b2, M, 128, 2);
    bn_zero<<<1, 128>>>();
    colstats<<<512, 128>>>(b2, M);
    bn_finalize<<<1, 128>>>(g4, be4, invM);
    bn_apply<false><<<gBN, 256>>>((const float4*)b2, (float4*)out_out, n4);
}

// round 3
// speedup vs baseline: 1.2837x; 1.2837x over previous
#include <cuda_runtime.h>
#include <cuda_bf16.h>
#include <cstdint>

#define NN   50000
#define EE   1600000
#define MTILES 391            // ceil(50000/128)

// ---------------- scratch (static device globals) ---------------------------
__device__ __align__(256) float g_b0[(size_t)NN * 128];
__device__ __align__(256) float g_b1[(size_t)NN * 128];
__device__ __align__(256) float g_b2[(size_t)NN * 128];
__device__ __align__(256) __nv_bfloat16 g_ah[(size_t)NN * 256];
__device__ __align__(256) __nv_bfloat16 g_al[(size_t)NN * 256];
__device__ __align__(256) __nv_bfloat16 g_bwh[4 * 128 * 256];
__device__ __align__(256) __nv_bfloat16 g_bwl[4 * 128 * 256];
__device__ int g_deg[NN];
__device__ int g_rowptr[NN + 1];
__device__ int g_pos[NN];
__device__ int g_col[EE];
__device__ __align__(16) float g_sum[128];
__device__ __align__(16) float g_ss[128];
__device__ __align__(16) float g_scale[128];
__device__ __align__(16) float g_shift[128];

// ---------------- small PTX helpers ------------------------------------------
__device__ __forceinline__ uint32_t s2u(const void* p) {
    uint32_t a;
    asm("{ .reg .u64 t; cvta.to.shared.u64 t, %1; cvt.u32.u64 %0, t; }"
        : "=r"(a) : "l"(p));
    return a;
}

#define LDSM4(r, addr)                                                         \
    asm volatile("ldmatrix.sync.aligned.m8n8.x4.shared.b16 {%0,%1,%2,%3}, [%4];" \
                 : "=r"((r)[0]), "=r"((r)[1]), "=r"((r)[2]), "=r"((r)[3])      \
                 : "r"(addr))

__device__ __forceinline__ void mma16816(float* c, const uint32_t* a,
                                         uint32_t b0, uint32_t b1) {
    asm volatile(
        "mma.sync.aligned.m16n8k16.row.col.f32.bf16.bf16.f32 "
        "{%0,%1,%2,%3}, {%4,%5,%6,%7}, {%8,%9}, {%0,%1,%2,%3};"
        : "+f"(c[0]), "+f"(c[1]), "+f"(c[2]), "+f"(c[3])
        : "r"(a[0]), "r"(a[1]), "r"(a[2]), "r"(a[3]), "r"(b0), "r"(b1));
}

__device__ __forceinline__ void cp16(uint32_t saddr, const void* g, int sz) {
    asm volatile("cp.async.cg.shared.global [%0], [%1], 16, %2;"
                 :: "r"(saddr), "l"(g), "r"(sz));
}
__device__ __forceinline__ void cp_commit() {
    asm volatile("cp.async.commit_group;");
}

// ---------------- bf16 split helpers -----------------------------------------
__device__ __forceinline__ uint32_t cvt2(float lo, float hi) {
    uint32_t r;
    asm("cvt.rn.bf16x2.f32 %0, %1, %2;" : "=r"(r) : "f"(hi), "f"(lo));
    return r;
}
__device__ __forceinline__ void split4(float4 v, uint2& h, uint2& l) {
    uint32_t h0 = cvt2(v.x, v.y);
    uint32_t h1 = cvt2(v.z, v.w);
    float hx = __uint_as_float(h0 << 16);
    float hy = __uint_as_float(h0 & 0xffff0000u);
    float hz = __uint_as_float(h1 << 16);
    float hw = __uint_as_float(h1 & 0xffff0000u);
    h.x = h0; h.y = h1;
    l.x = cvt2(v.x - hx, v.y - hy);
    l.y = cvt2(v.z - hz, v.w - hw);
}

// ---------------- conversions -------------------------------------------------
__global__ void conv_x(const float4* __restrict__ x) {
    int i = blockIdx.x * blockDim.x + threadIdx.x;
    if (i >= NN * 64) return;
    float4 v = __ldg(&x[i]);
    uint2 h, l;
    split4(v, h, l);
    *(uint2*)(g_ah + (size_t)i * 4) = h;
    *(uint2*)(g_al + (size_t)i * 4) = l;
}

__global__ void prep_w(const float* __restrict__ Wi, const float* __restrict__ Wh,
                       const float* __restrict__ Wl1, const float* __restrict__ Wr1,
                       const float* __restrict__ Wl2, const float* __restrict__ Wr2) {
    int t = blockIdx.x * blockDim.x + threadIdx.x;   // 0..131071
    int mat = t >> 15;
    int r = t & 32767;
    int n = r >> 8;
    int k = r & 255;
    float v = 0.f;
    if (mat == 0) v = Wi[k * 128 + n];
    else if (mat == 1) { if (k < 128) v = Wh[k * 128 + n]; }
    else if (mat == 2) v = (k < 128) ? Wl1[k * 128 + n] : Wr1[(k - 128) * 128 + n];
    else               v = (k < 128) ? Wl2[k * 128 + n] : Wr2[(k - 128) * 128 + n];
    __nv_bfloat16 h = __float2bfloat16(v);
    float res = v - __bfloat162float(h);
    g_bwh[mat * 32768 + n * 256 + k] = h;
    g_bwl[mat * 32768 + n * 256 + k] = __float2bfloat16(res);
}

// ---------------- HMMA GEMM (bf16x3 split, virtual-k pipeline) ---------------
// C[NN,128] = A[NN,K] @ B[K,128] + bias, with A-hi/lo and B-hi/lo split.
// Virtual k stages: vk%3 in {AhBh, AhBl, AlBh}; kk = (vk/3)*32.
// Block tile 128x128, BK=32, 8 warps (4m x 2n), warp tile 32x64, 3-stage cp.async.
#define BKG 32
#define STAGES 3
#define STAGE_BYTES 16384     // A tile 8KB + B tile 8KB

struct GemmArgs {
    const __nv_bfloat16 *ah, *al, *bh, *bl;
};

__device__ __forceinline__ void gemm_issue(const GemmArgs& ga, uint32_t sb,
                                           int vk, int m0, int tid) {
    int c3 = vk % 3;
    int kk = (vk / 3) * BKG;
    const __nv_bfloat16* A = (c3 == 2) ? ga.al : ga.ah;
    const __nv_bfloat16* B = (c3 == 1) ? ga.bl : ga.bh;
    uint32_t abase = sb + (vk % STAGES) * STAGE_BYTES;
    uint32_t bbase = abase + 8192;
#pragma unroll
    for (int i = 0; i < 2; i++) {
        int unit = tid + i * 256;
        int row = unit >> 2, c = unit & 3;
        uint32_t saddr = abase + row * 64 + ((c ^ (row & 3)) << 4);
        int grow = m0 + row;
        int ok = grow < NN;
        const void* g = A + (size_t)(ok ? grow : 0) * 256 + kk + c * 8;
        cp16(saddr, g, ok ? 16 : 0);
    }
#pragma unroll
    for (int i = 0; i < 2; i++) {
        int unit = tid + i * 256;
        int row = unit >> 2, c = unit & 3;
        uint32_t saddr = bbase + row * 64 + ((c ^ (row & 3)) << 4);
        const void* g = B + (size_t)row * 256 + kk + c * 8;
        cp16(saddr, g, 16);
    }
    cp_commit();
}

__global__ void __launch_bounds__(256, 2) gemm_mma(
    const __nv_bfloat16* __restrict__ ah, const __nv_bfloat16* __restrict__ al,
    const __nv_bfloat16* __restrict__ bh, const __nv_bfloat16* __restrict__ bl,
    const float* __restrict__ bias, float* __restrict__ C, int K)
{
    extern __shared__ char smem[];
    const uint32_t sb = s2u(smem);
    const int tid = threadIdx.x;
    const int lane = tid & 31;
    const int wid = tid >> 5;
    const int wm = wid & 3;        // 4 m-stripes of 32
    const int wn = wid >> 2;       // 2 n-stripes of 64
    const int m0 = blockIdx.x * 128;
    const int NV = 3 * (K >> 5);

    GemmArgs ga = {ah, al, bh, bl};

    float acc[2][8][4];
#pragma unroll
    for (int i = 0; i < 2; i++)
#pragma unroll
        for (int j = 0; j < 8; j++)
#pragma unroll
            for (int q = 0; q < 4; q++) acc[i][j][q] = 0.f;

#pragma unroll
    for (int s = 0; s < STAGES; s++) gemm_issue(ga, sb, s, m0, tid);

    for (int vk = 0; vk < NV; vk++) {
        asm volatile("cp.async.wait_group %0;" :: "n"(STAGES - 1));
        __syncthreads();
        uint32_t abase = sb + (vk % STAGES) * STAGE_BYTES;
        uint32_t bbase = abase + 8192;
#pragma unroll
        for (int k16 = 0; k16 < 2; k16++) {
            uint32_t a_r[2][4], b_r[4][4];
            int g = lane >> 3;
#pragma unroll
            for (int mf = 0; mf < 2; mf++) {
                int row = wm * 32 + mf * 16 + ((g & 1) << 3) + (lane & 7);
                int c = k16 * 2 + (g >> 1);
                uint32_t addr = abase + row * 64 + ((c ^ (row & 3)) << 4);
                LDSM4(a_r[mf], addr);
            }
#pragma unroll
            for (int nf = 0; nf < 4; nf++) {
                int row = wn * 64 + nf * 16 + ((g >> 1) << 3) + (lane & 7);
                int c = k16 * 2 + (g & 1);
                uint32_t addr = bbase + row * 64 + ((c ^ (row & 3)) << 4);
                LDSM4(b_r[nf], addr);
            }
#pragma unroll
            for (int mf = 0; mf < 2; mf++)
#pragma unroll
                for (int nf = 0; nf < 4; nf++) {
                    mma16816(acc[mf][nf * 2],     a_r[mf], b_r[nf][0], b_r[nf][1]);
                    mma16816(acc[mf][nf * 2 + 1], a_r[mf], b_r[nf][2], b_r[nf][3]);
                }
        }
        __syncthreads();
        if (vk + STAGES < NV) gemm_issue(ga, sb, vk + STAGES, m0, tid);
        else cp_commit();
    }

    // epilogue: acc[mf][nf8]: rows m0+wm*32+mf*16+(lane>>2)(+8), cols wn*64+nf8*8+(lane&3)*2
#pragma unroll
    for (int mf = 0; mf < 2; mf++) {
#pragma unroll
        for (int nf8 = 0; nf8 < 8; nf8++) {
            int col = wn * 64 + nf8 * 8 + (lane & 3) * 2;
            float bx = __ldg(bias + col);
            float by = __ldg(bias + col + 1);
            int r0 = m0 + wm * 32 + mf * 16 + (lane >> 2);
            if (r0 < NN) {
                float2 v = make_float2(acc[mf][nf8][0] + bx, acc[mf][nf8][1] + by);
                *(float2*)(C + (size_t)r0 * 128 + col) = v;
            }
            int r1 = r0 + 8;
            if (r1 < NN) {
                float2 v = make_float2(acc[mf][nf8][2] + bx, acc[mf][nf8][3] + by);
                *(float2*)(C + (size_t)r1 * 128 + col) = v;
            }
        }
    }
}

// ---------------- BatchNorm pipeline ------------------------------------------
__global__ void bn_zero() {
    int t = threadIdx.x;
    g_sum[t] = 0.f;
    g_ss[t] = 0.f;
}

__global__ void colstats(const float* __restrict__ X, int M) {
    int c = threadIdx.x;
    float s = 0.f, ss = 0.f;
    for (int r = blockIdx.x; r < M; r += gridDim.x) {
        float v = X[(size_t)r * 128 + c];
        s += v;
        ss += v * v;
    }
    atomicAdd(&g_sum[c], s);
    atomicAdd(&g_ss[c], ss);
}

__global__ void bn_finalize(const float* __restrict__ g,
                            const float* __restrict__ be, float invM) {
    int c = threadIdx.x;
    float mean = g_sum[c] * invM;
    float var = fmaf(-mean, mean, g_ss[c] * invM);
    float r = rsqrtf(var + 1e-5f);
    float sc = g[c] * r;
    g_scale[c] = sc;
    g_shift[c] = be[c] - mean * sc;
}

// fused BN apply: fp32 out (optional) + bf16 hi/lo split out (optional)
template <bool RELU, bool WF32, bool WBF16>
__global__ void bn_apply(const float4* __restrict__ X, float4* __restrict__ Y,
                         int colofs, int n4) {
    int i = blockIdx.x * blockDim.x + threadIdx.x;
    if (i >= n4) return;
    int gsel = i & 31;
    float4 sc = __ldg((const float4*)g_scale + gsel);
    float4 sh = __ldg((const float4*)g_shift + gsel);
    float4 v = X[i];
    float4 r;
    r.x = fmaf(v.x, sc.x, sh.x);
    r.y = fmaf(v.y, sc.y, sh.y);
    r.z = fmaf(v.z, sc.z, sh.z);
    r.w = fmaf(v.w, sc.w, sh.w);
    if (RELU) {
        r.x = fmaxf(r.x, 0.f);
        r.y = fmaxf(r.y, 0.f);
        r.z = fmaxf(r.z, 0.f);
        r.w = fmaxf(r.w, 0.f);
    }
    if (WF32) Y[i] = r;
    if (WBF16) {
        int row = i >> 5;
        int c = (i & 31) * 4;
        size_t base = (size_t)row * 256 + colofs + c;
        uint2 h, l;
        split4(r, h, l);
        *(uint2*)(g_ah + base) = h;
        *(uint2*)(g_al + base) = l;
    }
}

// ---------------- CSR build -----------------------------------------------------
__global__ void zero_deg() {
    int i = blockIdx.x * blockDim.x + threadIdx.x;
    if (i < NN) g_deg[i] = 0;
}

__global__ void count_deg(const int* __restrict__ dst) {
    for (int e = blockIdx.x * blockDim.x + threadIdx.x; e < EE;
         e += gridDim.x * blockDim.x)
        atomicAdd(&g_deg[__ldg(&dst[e])], 1);
}

__global__ void __launch_bounds__(1024, 1) scan_deg() {
    __shared__ int wsum[32];
    int tid = threadIdx.x, lane = tid & 31, wid = tid >> 5;
    const int CH = (NN + 1023) >> 10;   // 49
    int start = tid * CH;
    int arr[49];
#pragma unroll
    for (int i = 0; i < 49; i++) {
        int idx = start + i;
        arr[i] = (idx < NN) ? g_deg[idx] : 0;
    }
    int s = 0;
#pragma unroll
    for (int i = 0; i < 49; i++) s += arr[i];
    int v = s;
#pragma unroll
    for (int off = 1; off < 32; off <<= 1) {
        int t = __shfl_up_sync(0xffffffffu, v, off);
        if (lane >= off) v += t;
    }
    if (lane == 31) wsum[wid] = v;
    __syncthreads();
    if (wid == 0) {
        int w = wsum[lane];
#pragma unroll
        for (int off = 1; off < 32; off <<= 1) {
            int t = __shfl_up_sync(0xffffffffu, w, off);
            if (lane >= off) w += t;
        }
        wsum[lane] = w;
    }
    __syncthreads();
    int run = (wid ? wsum[wid - 1] : 0) + (v - s);
#pragma unroll
    for (int i = 0; i < 49; i++) {
        int idx = start + i;
        if (idx < NN) {
            g_rowptr[idx] = run;
            g_pos[idx] = run;
            run += arr[i];
        }
    }
    if (tid == 1023) g_rowptr[NN] = run;
}

__global__ void fill_csr(const int* __restrict__ src, const int* __restrict__ dst) {
    for (int e = blockIdx.x * blockDim.x + threadIdx.x; e < EE;
         e += gridDim.x * blockDim.x) {
        int d = __ldg(&dst[e]);
        int p = atomicAdd(&g_pos[d], 1);
        g_col[p] = __ldg(&src[e]);
    }
}

// ---------------- SAGE mean aggregation: warp/node, bf16-split output ----------
__global__ void sage_agg(const float4* __restrict__ feat) {
    int gw = (blockIdx.x * blockDim.x + threadIdx.x) >> 5;
    int lane = threadIdx.x & 31;
    if (gw >= NN) return;
    int beg = g_rowptr[gw], end = g_rowptr[gw + 1];
    float4 acc = make_float4(0.f, 0.f, 0.f, 0.f);
#pragma unroll 4
    for (int e = beg; e < end; e++) {
        int s = __ldg(&g_col[e]);
        float4 v = __ldg(&feat[(size_t)s * 32 + lane]);
        acc.x += v.x; acc.y += v.y; acc.z += v.z; acc.w += v.w;
    }
    int d = end - beg;
    float inv = 1.0f / (float)(d > 0 ? d : 1);
    acc.x *= inv; acc.y *= inv; acc.z *= inv; acc.w *= inv;
    uint2 h, l;
    split4(acc, h, l);
    size_t base = (size_t)gw * 256 + lane * 4;
    *(uint2*)(g_ah + base) = h;
    *(uint2*)(g_al + base) = l;
}

// ---------------- launch ---------------------------------------------------------
extern "C" void kernel_launch(void* const* d_in, const int* in_sizes, int n_in,
                              void* d_out, int out_size) {
    const float* x     = (const float*)d_in[0];
    const int*   ei    = (const int*)d_in[1];
    const float* W_in  = (const float*)d_in[2];
    const float* b_in  = (const float*)d_in[3];
    const float* g1    = (const float*)d_in[4];
    const float* be1   = (const float*)d_in[5];
    const float* W_hid = (const float*)d_in[6];
    const float* b_hid = (const float*)d_in[7];
    const float* g2    = (const float*)d_in[8];
    const float* be2   = (const float*)d_in[9];
    const float* Wl1   = (const float*)d_in[10];
    const float* bl1   = (const float*)d_in[11];
    const float* Wr1   = (const float*)d_in[12];
    const float* g3    = (const float*)d_in[13];
    const float* be3   = (const float*)d_in[14];
    const float* Wl2   = (const float*)d_in[15];
    const float* bl2   = (const float*)d_in[16];
    const float* Wr2   = (const float*)d_in[17];
    const float* g4    = (const float*)d_in[18];
    const float* be4   = (const float*)d_in[19];

    const int* src = ei;
    const int* dst = ei + EE;
    float* out_feat = (float*)d_out;
    float* out_out  = out_feat + (size_t)NN * 128;

    void *p0, *p1, *p2, *pah, *pal, *pbh, *pbl;
    cudaGetSymbolAddress(&p0, g_b0);
    cudaGetSymbolAddress(&p1, g_b1);
    cudaGetSymbolAddress(&p2, g_b2);
    cudaGetSymbolAddress(&pah, g_ah);
    cudaGetSymbolAddress(&pal, g_al);
    cudaGetSymbolAddress(&pbh, g_bwh);
    cudaGetSymbolAddress(&pbl, g_bwl);
    float* b0 = (float*)p0;
    float* b1 = (float*)p1;
    float* b2 = (float*)p2;
    __nv_bfloat16* ah = (__nv_bfloat16*)pah;
    __nv_bfloat16* al = (__nv_bfloat16*)pal;
    __nv_bfloat16* bwh = (__nv_bfloat16*)pbh;
    __nv_bfloat16* bwl = (__nv_bfloat16*)pbl;

    const int n4 = NN * 32;
    const int gBN = (n4 + 255) / 256;
    const float invM = 1.0f / (float)NN;
    const int GSMEM = STAGES * STAGE_BYTES;   // 48KB

    // weight prep + input conversion + CSR build
    prep_w<<<512, 256>>>(W_in, W_hid, Wl1, Wr1, Wl2, Wr2);
    conv_x<<<(NN * 64 + 255) / 256, 256>>>((const float4*)x);
    zero_deg<<<(NN + 255) / 256, 256>>>();
    count_deg<<<4096, 256>>>(dst);
    scan_deg<<<1, 1024>>>();
    fill_csr<<<4096, 256>>>(src, dst);

    // layer 1: relu(BN(x @ W_in + b_in)) -> bf16 split cols [0:128)
    gemm_mma<<<MTILES, 256, GSMEM>>>(ah, al, bwh, bwl, b_in, b0, 256);
    bn_zero<<<1, 128>>>();
    colstats<<<512, 128>>>(b0, NN);
    bn_finalize<<<1, 128>>>(g1, be1, invM);
    bn_apply<true, false, true><<<gBN, 256>>>((const float4*)b0, nullptr, 0, n4);

    // layer 2: feat = relu(BN(h @ W_hid + b_hid)) -> out_feat fp32 + bf16 [128:256)
    gemm_mma<<<MTILES, 256, GSMEM>>>(ah, al, bwh + 32768, bwl + 32768, b_hid, b1, 128);
    bn_zero<<<1, 128>>>();
    colstats<<<512, 128>>>(b1, NN);
    bn_finalize<<<1, 128>>>(g2, be2, invM);
    bn_apply<true, true, true><<<gBN, 256>>>((const float4*)b1, (float4*)out_feat, 128, n4);

    // SAGE 1: BN(mean_agg(feat) @ Wl1 + bl1 + feat @ Wr1)
    sage_agg<<<(NN * 32 + 255) / 256, 256>>>((const float4*)out_feat);
    gemm_mma<<<MTILES, 256, GSMEM>>>(ah, al, bwh + 2 * 32768, bwl + 2 * 32768, bl1, b2, 256);
    bn_zero<<<1, 128>>>();
    colstats<<<512, 128>>>(b2, NN);
    bn_finalize<<<1, 128>>>(g3, be3, invM);
    bn_apply<false, true, true><<<gBN, 256>>>((const float4*)b2, (float4*)b0, 128, n4);

    // SAGE 2: out = BN(mean_agg(o1) @ Wl2 + bl2 + o1 @ Wr2) -> out_out
    sage_agg<<<(NN * 32 + 255) / 256, 256>>>((const float4*)b0);
    gemm_mma<<<MTILES, 256, GSMEM>>>(ah, al, bwh + 3 * 32768, bwl + 3 * 32768, bl2, b1, 256);
    bn_zero<<<1, 128>>>();
    colstats<<<512, 128>>>(b1, NN);
    bn_finalize<<<1, 128>>>(g4, be4, invM);
    bn_apply<false, true, false><<<gBN, 256>>>((const float4*)b1, (float4*)out_out, 0, n4);
}

// round 4
// speedup vs baseline: 1.8205x; 1.4181x over previous
#include <cuda_runtime.h>
#include <cuda_bf16.h>
#include <cstdint>

#define NN   50000
#define EE   1600000
#define MTILES 391            // ceil(50000/128)

// ---------------- scratch (static device globals) ---------------------------
__device__ __align__(256) float g_b0[(size_t)NN * 128];
__device__ __align__(256) float g_b1[(size_t)NN * 128];
__device__ __align__(256) __nv_bfloat16 g_ah[(size_t)NN * 256];
__device__ __align__(256) __nv_bfloat16 g_al[(size_t)NN * 256];
__device__ __align__(256) __nv_bfloat16 g_bwh[4 * 128 * 256];
__device__ __align__(256) __nv_bfloat16 g_bwl[4 * 128 * 256];
__device__ int g_deg[NN];
__device__ int g_rowptr[NN + 1];
__device__ int g_pos[NN];
__device__ int g_col[EE];
__device__ __align__(16) float g_stats[1024];     // 4 sets x (sum[128], ss[128])
__device__ __align__(16) float g_scale[128];
__device__ __align__(16) float g_shift[128];

// ---------------- small PTX helpers ------------------------------------------
__device__ __forceinline__ uint32_t s2u(const void* p) {
    uint32_t a;
    asm("{ .reg .u64 t; cvta.to.shared.u64 t, %1; cvt.u32.u64 %0, t; }"
        : "=r"(a) : "l"(p));
    return a;
}

#define LDSM4(r, addr)                                                         \
    asm volatile("ldmatrix.sync.aligned.m8n8.x4.shared.b16 {%0,%1,%2,%3}, [%4];" \
                 : "=r"((r)[0]), "=r"((r)[1]), "=r"((r)[2]), "=r"((r)[3])      \
                 : "r"(addr))

__device__ __forceinline__ void mma16816(float* c, const uint32_t* a,
                                         uint32_t b0, uint32_t b1) {
    asm volatile(
        "mma.sync.aligned.m16n8k16.row.col.f32.bf16.bf16.f32 "
        "{%0,%1,%2,%3}, {%4,%5,%6,%7}, {%8,%9}, {%0,%1,%2,%3};"
        : "+f"(c[0]), "+f"(c[1]), "+f"(c[2]), "+f"(c[3])
        : "r"(a[0]), "r"(a[1]), "r"(a[2]), "r"(a[3]), "r"(b0), "r"(b1));
}

__device__ __forceinline__ void cp16(uint32_t saddr, const void* g, int sz) {
    asm volatile("cp.async.cg.shared.global [%0], [%1], 16, %2;"
                 :: "r"(saddr), "l"(g), "r"(sz));
}
__device__ __forceinline__ void cp_commit() {
    asm volatile("cp.async.commit_group;");
}

// ---------------- bf16 split helpers -----------------------------------------
__device__ __forceinline__ uint32_t cvt2(float lo, float hi) {
    uint32_t r;
    asm("cvt.rn.bf16x2.f32 %0, %1, %2;" : "=r"(r) : "f"(hi), "f"(lo));
    return r;
}
__device__ __forceinline__ void split4(float4 v, uint2& h, uint2& l) {
    uint32_t h0 = cvt2(v.x, v.y);
    uint32_t h1 = cvt2(v.z, v.w);
    float hx = __uint_as_float(h0 << 16);
    float hy = __uint_as_float(h0 & 0xffff0000u);
    float hz = __uint_as_float(h1 << 16);
    float hw = __uint_as_float(h1 & 0xffff0000u);
    h.x = h0; h.y = h1;
    l.x = cvt2(v.x - hx, v.y - hy);
    l.y = cvt2(v.z - hz, v.w - hw);
}

// ---------------- conversions -------------------------------------------------
__global__ void conv_x(const float4* __restrict__ x) {
    int i = blockIdx.x * blockDim.x + threadIdx.x;
    if (i >= NN * 64) return;
    float4 v = __ldg(&x[i]);
    uint2 h, l;
    split4(v, h, l);
    *(uint2*)(g_ah + (size_t)i * 4) = h;
    *(uint2*)(g_al + (size_t)i * 4) = l;
}

__global__ void prep_w(const float* __restrict__ Wi, const float* __restrict__ Wh,
                       const float* __restrict__ Wl1, const float* __restrict__ Wr1,
                       const float* __restrict__ Wl2, const float* __restrict__ Wr2) {
    int t = blockIdx.x * blockDim.x + threadIdx.x;   // 0..131071
    int mat = t >> 15;
    int r = t & 32767;
    int n = r >> 8;
    int k = r & 255;
    float v = 0.f;
    if (mat == 0) v = Wi[k * 128 + n];
    else if (mat == 1) { if (k < 128) v = Wh[k * 128 + n]; }
    else if (mat == 2) v = (k < 128) ? Wl1[k * 128 + n] : Wr1[(k - 128) * 128 + n];
    else               v = (k < 128) ? Wl2[k * 128 + n] : Wr2[(k - 128) * 128 + n];
    __nv_bfloat16 h = __float2bfloat16(v);
    float res = v - __bfloat162float(h);
    g_bwh[mat * 32768 + n * 256 + k] = h;
    g_bwl[mat * 32768 + n * 256 + k] = __float2bfloat16(res);
}

__global__ void zero_stats() {
    g_stats[threadIdx.x] = 0.f;
}

// ---------------- HMMA GEMM (bf16x3 split) + fused BN column stats -----------
#define BKG 32
#define STAGES 3
#define STAGE_BYTES 16384     // A tile 8KB + B tile 8KB
#define GSMEM (STAGES * STAGE_BYTES + 1024)

struct GemmArgs {
    const __nv_bfloat16 *ah, *al, *bh, *bl;
};

__device__ __forceinline__ void gemm_issue(const GemmArgs& ga, uint32_t sb,
                                           int vk, int m0, int tid) {
    int c3 = vk % 3;
    int kk = (vk / 3) * BKG;
    const __nv_bfloat16* A = (c3 == 2) ? ga.al : ga.ah;
    const __nv_bfloat16* B = (c3 == 1) ? ga.bl : ga.bh;
    uint32_t abase = sb + (vk % STAGES) * STAGE_BYTES;
    uint32_t bbase = abase + 8192;
#pragma unroll
    for (int i = 0; i < 2; i++) {
        int unit = tid + i * 256;
        int row = unit >> 2, c = unit & 3;
        uint32_t saddr = abase + row * 64 + ((c ^ (row & 3)) << 4);
        int grow = m0 + row;
        int ok = grow < NN;
        const void* g = A + (size_t)(ok ? grow : 0) * 256 + kk + c * 8;
        cp16(saddr, g, ok ? 16 : 0);
    }
#pragma unroll
    for (int i = 0; i < 2; i++) {
        int unit = tid + i * 256;
        int row = unit >> 2, c = unit & 3;
        uint32_t saddr = bbase + row * 64 + ((c ^ (row & 3)) << 4);
        const void* g = B + (size_t)row * 256 + kk + c * 8;
        cp16(saddr, g, 16);
    }
    cp_commit();
}

__global__ void __launch_bounds__(256, 2) gemm_mma(
    const __nv_bfloat16* __restrict__ ah, const __nv_bfloat16* __restrict__ al,
    const __nv_bfloat16* __restrict__ bh, const __nv_bfloat16* __restrict__ bl,
    const float* __restrict__ bias, float* __restrict__ C,
    float* __restrict__ st, int K)
{
    extern __shared__ char smem[];
    const uint32_t sb = s2u(smem);
    float* smem_stat = (float*)(smem + STAGES * STAGE_BYTES);
    const int tid = threadIdx.x;
    const int lane = tid & 31;
    const int wid = tid >> 5;
    const int wm = wid & 3;        // 4 m-stripes of 32
    const int wn = wid >> 2;       // 2 n-stripes of 64
    const int m0 = blockIdx.x * 128;
    const int NV = 3 * (K >> 5);

    if (tid < 256) smem_stat[tid] = 0.f;

    GemmArgs ga = {ah, al, bh, bl};

    float acc[2][8][4];
#pragma unroll
    for (int i = 0; i < 2; i++)
#pragma unroll
        for (int j = 0; j < 8; j++)
#pragma unroll
            for (int q = 0; q < 4; q++) acc[i][j][q] = 0.f;

#pragma unroll
    for (int s = 0; s < STAGES; s++) gemm_issue(ga, sb, s, m0, tid);

    for (int vk = 0; vk < NV; vk++) {
        asm volatile("cp.async.wait_group %0;" :: "n"(STAGES - 1));
        __syncthreads();
        uint32_t abase = sb + (vk % STAGES) * STAGE_BYTES;
        uint32_t bbase = abase + 8192;
#pragma unroll
        for (int k16 = 0; k16 < 2; k16++) {
            uint32_t a_r[2][4], b_r[4][4];
            int g = lane >> 3;
#pragma unroll
            for (int mf = 0; mf < 2; mf++) {
                int row = wm * 32 + mf * 16 + ((g & 1) << 3) + (lane & 7);
                int c = k16 * 2 + (g >> 1);
                uint32_t addr = abase + row * 64 + ((c ^ (row & 3)) << 4);
                LDSM4(a_r[mf], addr);
            }
#pragma unroll
            for (int nf = 0; nf < 4; nf++) {
                int row = wn * 64 + nf * 16 + ((g >> 1) << 3) + (lane & 7);
                int c = k16 * 2 + (g & 1);
                uint32_t addr = bbase + row * 64 + ((c ^ (row & 3)) << 4);
                LDSM4(b_r[nf], addr);
            }
#pragma unroll
            for (int mf = 0; mf < 2; mf++)
#pragma unroll
                for (int nf = 0; nf < 4; nf++) {
                    mma16816(acc[mf][nf * 2],     a_r[mf], b_r[nf][0], b_r[nf][1]);
                    mma16816(acc[mf][nf * 2 + 1], a_r[mf], b_r[nf][2], b_r[nf][3]);
                }
        }
        __syncthreads();
        if (vk + STAGES < NV) gemm_issue(ga, sb, vk + STAGES, m0, tid);
        else cp_commit();
    }

    // epilogue: store C (+bias) and accumulate raw column stats.
    // invalid rows (>= NN) hold exact zeros in acc (zfill A-tile) -> harmless in sums.
#pragma unroll
    for (int nf8 = 0; nf8 < 8; nf8++) {
        int col = wn * 64 + nf8 * 8 + (lane & 3) * 2;
        float bx = __ldg(bias + col);
        float by = __ldg(bias + col + 1);
        float s0 = 0.f, q0 = 0.f, s1 = 0.f, q1 = 0.f;
#pragma unroll
        for (int mf = 0; mf < 2; mf++) {
            float v0 = acc[mf][nf8][0], v1 = acc[mf][nf8][1];
            float v2 = acc[mf][nf8][2], v3 = acc[mf][nf8][3];
            s0 += v0 + v2; q0 += v0 * v0 + v2 * v2;
            s1 += v1 + v3; q1 += v1 * v1 + v3 * v3;
            int r0 = m0 + wm * 32 + mf * 16 + (lane >> 2);
            if (r0 < NN)
                *(float2*)(C + (size_t)r0 * 128 + col) = make_float2(v0 + bx, v1 + by);
            int r1 = r0 + 8;
            if (r1 < NN)
                *(float2*)(C + (size_t)r1 * 128 + col) = make_float2(v2 + bx, v3 + by);
        }
#pragma unroll
        for (int msk = 4; msk < 32; msk <<= 1) {
            s0 += __shfl_xor_sync(0xffffffffu, s0, msk);
            q0 += __shfl_xor_sync(0xffffffffu, q0, msk);
            s1 += __shfl_xor_sync(0xffffffffu, s1, msk);
            q1 += __shfl_xor_sync(0xffffffffu, q1, msk);
        }
        if ((lane >> 2) == 0) {
            atomicAdd(&smem_stat[col], s0);
            atomicAdd(&smem_stat[col + 1], s1);
            atomicAdd(&smem_stat[128 + col], q0);
            atomicAdd(&smem_stat[128 + col + 1], q1);
        }
    }
    __syncthreads();
    if (tid < 256) atomicAdd(st + tid, smem_stat[tid]);
}

// ---------------- BN finalize + apply -----------------------------------------
__global__ void bn_finalize(const float* __restrict__ st,
                            const float* __restrict__ bias,
                            const float* __restrict__ g,
                            const float* __restrict__ be, float invM) {
    int c = threadIdx.x;
    float mean_raw = st[c] * invM;
    float var = fmaf(-mean_raw, mean_raw, st[128 + c] * invM);
    float mean = mean_raw + bias[c];
    float r = rsqrtf(var + 1e-5f);
    float sc = g[c] * r;
    g_scale[c] = sc;
    g_shift[c] = be[c] - mean * sc;
}

template <bool RELU, bool WF32, bool WBF16>
__global__ void bn_apply(const float4* __restrict__ X, float4* __restrict__ Y,
                         int colofs, int n4) {
    int i = blockIdx.x * blockDim.x + threadIdx.x;
    if (i >= n4) return;
    int gsel = i & 31;
    float4 sc = __ldg((const float4*)g_scale + gsel);
    float4 sh = __ldg((const float4*)g_shift + gsel);
    float4 v = X[i];
    float4 r;
    r.x = fmaf(v.x, sc.x, sh.x);
    r.y = fmaf(v.y, sc.y, sh.y);
    r.z = fmaf(v.z, sc.z, sh.z);
    r.w = fmaf(v.w, sc.w, sh.w);
    if (RELU) {
        r.x = fmaxf(r.x, 0.f);
        r.y = fmaxf(r.y, 0.f);
        r.z = fmaxf(r.z, 0.f);
        r.w = fmaxf(r.w, 0.f);
    }
    if (WF32) Y[i] = r;
    if (WBF16) {
        int row = i >> 5;
        int c = (i & 31) * 4;
        size_t base = (size_t)row * 256 + colofs + c;
        uint2 h, l;
        split4(r, h, l);
        *(uint2*)(g_ah + base) = h;
        *(uint2*)(g_al + base) = l;
    }
}

// ---------------- CSR build -----------------------------------------------------
__global__ void zero_deg() {
    int i = blockIdx.x * blockDim.x + threadIdx.x;
    if (i < NN) g_deg[i] = 0;
}

__global__ void count_deg(const int* __restrict__ dst) {
    for (int e = blockIdx.x * blockDim.x + threadIdx.x; e < EE;
         e += gridDim.x * blockDim.x)
        atomicAdd(&g_deg[__ldg(&dst[e])], 1);
}

__global__ void __launch_bounds__(1024, 1) scan_deg() {
    __shared__ int wsum[32];
    int tid = threadIdx.x, lane = tid & 31, wid = tid >> 5;
    const int CH = (NN + 1023) >> 10;   // 49
    int start = tid * CH;
    int arr[49];
#pragma unroll
    for (int i = 0; i < 49; i++) {
        int idx = start + i;
        arr[i] = (idx < NN) ? g_deg[idx] : 0;
    }
    int s = 0;
#pragma unroll
    for (int i = 0; i < 49; i++) s += arr[i];
    int v = s;
#pragma unroll
    for (int off = 1; off < 32; off <<= 1) {
        int t = __shfl_up_sync(0xffffffffu, v, off);
        if (lane >= off) v += t;
    }
    if (lane == 31) wsum[wid] = v;
    __syncthreads();
    if (wid == 0) {
        int w = wsum[lane];
#pragma unroll
        for (int off = 1; off < 32; off <<= 1) {
            int t = __shfl_up_sync(0xffffffffu, w, off);
            if (lane >= off) w += t;
        }
        wsum[lane] = w;
    }
    __syncthreads();
    int run = (wid ? wsum[wid - 1] : 0) + (v - s);
#pragma unroll
    for (int i = 0; i < 49; i++) {
        int idx = start + i;
        if (idx < NN) {
            g_rowptr[idx] = run;
            g_pos[idx] = run;
            run += arr[i];
        }
    }
    if (tid == 1023) g_rowptr[NN] = run;
}

__global__ void fill_csr(const int* __restrict__ src, const int* __restrict__ dst) {
    for (int e = blockIdx.x * blockDim.x + threadIdx.x; e < EE;
         e += gridDim.x * blockDim.x) {
        int d = __ldg(&dst[e]);
        int p = atomicAdd(&g_pos[d], 1);
        g_col[p] = __ldg(&src[e]);
    }
}

// ---------------- SAGE mean aggregation from bf16-hi, split output ------------
__global__ void sage_agg_h(int in_ofs) {
    int gw = (blockIdx.x * blockDim.x + threadIdx.x) >> 5;
    int lane = threadIdx.x & 31;
    if (gw >= NN) return;
    int beg = g_rowptr[gw], end = g_rowptr[gw + 1];
    float a0 = 0.f, a1 = 0.f, a2 = 0.f, a3 = 0.f;
#pragma unroll 4
    for (int e = beg; e < end; e++) {
        int s = __ldg(&g_col[e]);
        uint2 v = __ldg((const uint2*)(g_ah + (size_t)s * 256 + in_ofs + lane * 4));
        a0 += __uint_as_float(v.x << 16);
        a1 += __uint_as_float(v.x & 0xffff0000u);
        a2 += __uint_as_float(v.y << 16);
        a3 += __uint_as_float(v.y & 0xffff0000u);
    }
    int d = end - beg;
    float inv = 1.0f / (float)(d > 0 ? d : 1);
    float4 acc = make_float4(a0 * inv, a1 * inv, a2 * inv, a3 * inv);
    uint2 h, l;
    split4(acc, h, l);
    size_t base = (size_t)gw * 256 + lane * 4;
    *(uint2*)(g_ah + base) = h;
    *(uint2*)(g_al + base) = l;
}

// ---------------- launch ---------------------------------------------------------
extern "C" void kernel_launch(void* const* d_in, const int* in_sizes, int n_in,
                              void* d_out, int out_size) {
    const float* x     = (const float*)d_in[0];
    const int*   ei    = (const int*)d_in[1];
    const float* W_in  = (const float*)d_in[2];
    const float* b_in  = (const float*)d_in[3];
    const float* g1    = (const float*)d_in[4];
    const float* be1   = (const float*)d_in[5];
    const float* W_hid = (const float*)d_in[6];
    const float* b_hid = (const float*)d_in[7];
    const float* g2    = (const float*)d_in[8];
    const float* be2   = (const float*)d_in[9];
    const float* Wl1   = (const float*)d_in[10];
    const float* bl1   = (const float*)d_in[11];
    const float* Wr1   = (const float*)d_in[12];
    const float* g3    = (const float*)d_in[13];
    const float* be3   = (const float*)d_in[14];
    const float* Wl2   = (const float*)d_in[15];
    const float* bl2   = (const float*)d_in[16];
    const float* Wr2   = (const float*)d_in[17];
    const float* g4    = (const float*)d_in[18];
    const float* be4   = (const float*)d_in[19];

    const int* src = ei;
    const int* dst = ei + EE;
    float* out_feat = (float*)d_out;
    float* out_out  = out_feat + (size_t)NN * 128;

    void *p0, *p1, *pah, *pal, *pbh, *pbl, *pst;
    cudaGetSymbolAddress(&p0, g_b0);
    cudaGetSymbolAddress(&p1, g_b1);
    cudaGetSymbolAddress(&pah, g_ah);
    cudaGetSymbolAddress(&pal, g_al);
    cudaGetSymbolAddress(&pbh, g_bwh);
    cudaGetSymbolAddress(&pbl, g_bwl);
    cudaGetSymbolAddress(&pst, g_stats);
    float* b0 = (float*)p0;
    float* b1 = (float*)p1;
    __nv_bfloat16* ah = (__nv_bfloat16*)pah;
    __nv_bfloat16* al = (__nv_bfloat16*)pal;
    __nv_bfloat16* bwh = (__nv_bfloat16*)pbh;
    __nv_bfloat16* bwl = (__nv_bfloat16*)pbl;
    float* st = (float*)pst;

    static cudaStream_t s_csr = nullptr;
    static cudaEvent_t ev_fork = nullptr, ev_csr = nullptr;
    static bool setup_done = false;
    if (!setup_done) {
        cudaFuncSetAttribute(gemm_mma, cudaFuncAttributeMaxDynamicSharedMemorySize,
                             GSMEM);
        cudaStreamCreateWithFlags(&s_csr, cudaStreamNonBlocking);
        cudaEventCreateWithFlags(&ev_fork, cudaEventDisableTiming);
        cudaEventCreateWithFlags(&ev_csr, cudaEventDisableTiming);
        setup_done = true;
    }

    const int n4 = NN * 32;
    const int gBN = (n4 + 255) / 256;
    const float invM = 1.0f / (float)NN;

    // ---- fork: CSR build on side stream (independent of layers 1-2) ----
    cudaEventRecord(ev_fork, 0);
    cudaStreamWaitEvent(s_csr, ev_fork, 0);
    zero_deg<<<(NN + 255) / 256, 256, 0, s_csr>>>();
    count_deg<<<4096, 256, 0, s_csr>>>(dst);
    scan_deg<<<1, 1024, 0, s_csr>>>();
    fill_csr<<<4096, 256, 0, s_csr>>>(src, dst);
    cudaEventRecord(ev_csr, s_csr);

    // ---- main stream: prep + layers 1-2 ----
    zero_stats<<<1, 1024>>>();
    prep_w<<<512, 256>>>(W_in, W_hid, Wl1, Wr1, Wl2, Wr2);
    conv_x<<<(NN * 64 + 255) / 256, 256>>>((const float4*)x);

    // layer 1: relu(BN(x @ W_in + b_in)) -> bf16 split cols [0:128)
    gemm_mma<<<MTILES, 256, GSMEM>>>(ah, al, bwh, bwl, b_in, b0, st, 256);
    bn_finalize<<<1, 128>>>(st, b_in, g1, be1, invM);
    bn_apply<true, false, true><<<gBN, 256>>>((const float4*)b0, nullptr, 0, n4);

    // layer 2: feat = relu(BN(h @ W_hid + b_hid)) -> out_feat fp32 + split [128:256)
    gemm_mma<<<MTILES, 256, GSMEM>>>(ah, al, bwh + 32768, bwl + 32768, b_hid, b1,
                                     st + 256, 128);
    bn_finalize<<<1, 128>>>(st + 256, b_hid, g2, be2, invM);
    bn_apply<true, true, true><<<gBN, 256>>>((const float4*)b1, (float4*)out_feat,
                                             128, n4);

    // ---- join CSR before first aggregation ----
    cudaStreamWaitEvent(0, ev_csr, 0);

    // SAGE 1: BN(mean_agg(feat) @ Wl1 + bl1 + feat @ Wr1) -> split [128:256)
    sage_agg_h<<<(NN * 32 + 255) / 256, 256>>>(128);
    gemm_mma<<<MTILES, 256, GSMEM>>>(ah, al, bwh + 2 * 32768, bwl + 2 * 32768, bl1,
                                     b0, st + 512, 256);
    bn_finalize<<<1, 128>>>(st + 512, bl1, g3, be3, invM);
    bn_apply<false, false, true><<<gBN, 256>>>((const float4*)b0, nullptr, 128, n4);

    // SAGE 2: out = BN(mean_agg(o1) @ Wl2 + bl2 + o1 @ Wr2) -> out_out
    sage_agg_h<<<(NN * 32 + 255) / 256, 256>>>(128);
    gemm_mma<<<MTILES, 256, GSMEM>>>(ah, al, bwh + 3 * 32768, bwl + 3 * 32768, bl2,
                                     b1, st + 768, 256);
    bn_finalize<<<1, 128>>>(st + 768, bl2, g4, be4, invM);
    bn_apply<false, true, false><<<gBN, 256>>>((const float4*)b1, (float4*)out_out,
                                               0, n4);
}

// round 5
// speedup vs baseline: 2.3643x; 1.2987x over previous
#include <cuda_runtime.h>
#include <cuda_bf16.h>
#include <cstdint>

#define NN   50000
#define EE   1600000
#define MTILES 391            // ceil(50000/128)

// ---------------- scratch (static device globals) ---------------------------
__device__ __align__(256) float g_b0[(size_t)NN * 128];
__device__ __align__(256) float g_b1[(size_t)NN * 128];
__device__ __align__(256) __nv_bfloat16 g_ah[(size_t)NN * 256];
__device__ __align__(256) __nv_bfloat16 g_al[(size_t)NN * 256];
__device__ __align__(256) __nv_bfloat16 g_bwh[4 * 128 * 256];
__device__ __align__(256) __nv_bfloat16 g_bwl[4 * 128 * 256];
__device__ int g_deg[NN];
__device__ int g_rowptr[NN + 1];
__device__ int g_pos[NN];
__device__ int g_col[EE];
__device__ __align__(16) float g_stats[1024];     // 4 sets x (sum[128], ss[128])
__device__ __align__(16) float g_scale[128];
__device__ __align__(16) float g_shift[128];

// ---------------- small PTX helpers ------------------------------------------
__device__ __forceinline__ uint32_t s2u(const void* p) {
    uint32_t a;
    asm("{ .reg .u64 t; cvta.to.shared.u64 t, %1; cvt.u32.u64 %0, t; }"
        : "=r"(a) : "l"(p));
    return a;
}

#define LDSM4(r, addr)                                                         \
    asm volatile("ldmatrix.sync.aligned.m8n8.x4.shared.b16 {%0,%1,%2,%3}, [%4];" \
                 : "=r"((r)[0]), "=r"((r)[1]), "=r"((r)[2]), "=r"((r)[3])      \
                 : "r"(addr))

__device__ __forceinline__ void mma16816(float* c, const uint32_t* a,
                                         uint32_t b0, uint32_t b1) {
    asm volatile(
        "mma.sync.aligned.m16n8k16.row.col.f32.bf16.bf16.f32 "
        "{%0,%1,%2,%3}, {%4,%5,%6,%7}, {%8,%9}, {%0,%1,%2,%3};"
        : "+f"(c[0]), "+f"(c[1]), "+f"(c[2]), "+f"(c[3])
        : "r"(a[0]), "r"(a[1]), "r"(a[2]), "r"(a[3]), "r"(b0), "r"(b1));
}

__device__ __forceinline__ void cp16(uint32_t saddr, const void* g, int sz) {
    asm volatile("cp.async.cg.shared.global [%0], [%1], 16, %2;"
                 :: "r"(saddr), "l"(g), "r"(sz));
}
__device__ __forceinline__ void cp_commit() {
    asm volatile("cp.async.commit_group;");
}

// ---------------- bf16 split helpers -----------------------------------------
__device__ __forceinline__ uint32_t cvt2(float lo, float hi) {
    uint32_t r;
    asm("cvt.rn.bf16x2.f32 %0, %1, %2;" : "=r"(r) : "f"(hi), "f"(lo));
    return r;
}
__device__ __forceinline__ void split4(float4 v, uint2& h, uint2& l) {
    uint32_t h0 = cvt2(v.x, v.y);
    uint32_t h1 = cvt2(v.z, v.w);
    float hx = __uint_as_float(h0 << 16);
    float hy = __uint_as_float(h0 & 0xffff0000u);
    float hz = __uint_as_float(h1 << 16);
    float hw = __uint_as_float(h1 & 0xffff0000u);
    h.x = h0; h.y = h1;
    l.x = cvt2(v.x - hx, v.y - hy);
    l.y = cvt2(v.z - hz, v.w - hw);
}

// ---------------- weight prep ---------------------------------------------------
__global__ void prep_w(const float* __restrict__ Wi, const float* __restrict__ Wh,
                       const float* __restrict__ Wl1, const float* __restrict__ Wr1,
                       const float* __restrict__ Wl2, const float* __restrict__ Wr2) {
    int t = blockIdx.x * blockDim.x + threadIdx.x;   // 0..131071
    int mat = t >> 15;
    int r = t & 32767;
    int n = r >> 8;
    int k = r & 255;
    float v = 0.f;
    if (mat == 0) v = Wi[k * 128 + n];
    else if (mat == 1) { if (k < 128) v = Wh[k * 128 + n]; }
    else if (mat == 2) v = (k < 128) ? Wl1[k * 128 + n] : Wr1[(k - 128) * 128 + n];
    else               v = (k < 128) ? Wl2[k * 128 + n] : Wr2[(k - 128) * 128 + n];
    __nv_bfloat16 h = __float2bfloat16(v);
    float res = v - __bfloat162float(h);
    g_bwh[mat * 32768 + n * 256 + k] = h;
    g_bwl[mat * 32768 + n * 256 + k] = __float2bfloat16(res);
}

__global__ void zero_stats() {
    g_stats[threadIdx.x] = 0.f;
}

// ---------------- shared GEMM pieces --------------------------------------------
// stage layout (32KB): Ah@0, Al@8K, Bh@16K, Bl@24K. row stride 64B, 16B-chunk swizzle.
#define STG 32768

__device__ __forceinline__ void mma_stage(uint32_t base, int lane, int wm, int wn,
                                          float (&acc)[2][8][4]) {
#pragma unroll
    for (int k16 = 0; k16 < 2; k16++) {
        int g = lane >> 3;
        uint32_t ah_r[2][4], al_r[2][4], b_r[4][4];
#pragma unroll
        for (int mf = 0; mf < 2; mf++) {
            int row = wm * 32 + mf * 16 + ((g & 1) << 3) + (lane & 7);
            int c = k16 * 2 + (g >> 1);
            uint32_t off = row * 64 + ((c ^ (row & 3)) << 4);
            LDSM4(ah_r[mf], base + off);
            LDSM4(al_r[mf], base + 8192 + off);
        }
#pragma unroll
        for (int nf = 0; nf < 4; nf++) {
            int row = wn * 64 + nf * 16 + ((g >> 1) << 3) + (lane & 7);
            int c = k16 * 2 + (g & 1);
            LDSM4(b_r[nf], base + 16384 + row * 64 + ((c ^ (row & 3)) << 4));
        }
#pragma unroll
        for (int mf = 0; mf < 2; mf++)
#pragma unroll
            for (int nf = 0; nf < 4; nf++) {
                mma16816(acc[mf][nf * 2],     ah_r[mf], b_r[nf][0], b_r[nf][1]);
                mma16816(acc[mf][nf * 2 + 1], ah_r[mf], b_r[nf][2], b_r[nf][3]);
                mma16816(acc[mf][nf * 2],     al_r[mf], b_r[nf][0], b_r[nf][1]);
                mma16816(acc[mf][nf * 2 + 1], al_r[mf], b_r[nf][2], b_r[nf][3]);
            }
#pragma unroll
        for (int nf = 0; nf < 4; nf++) {
            int row = wn * 64 + nf * 16 + ((g >> 1) << 3) + (lane & 7);
            int c = k16 * 2 + (g & 1);
            LDSM4(b_r[nf], base + 24576 + row * 64 + ((c ^ (row & 3)) << 4));
        }
#pragma unroll
        for (int mf = 0; mf < 2; mf++)
#pragma unroll
            for (int nf = 0; nf < 4; nf++) {
                mma16816(acc[mf][nf * 2],     ah_r[mf], b_r[nf][0], b_r[nf][1]);
                mma16816(acc[mf][nf * 2 + 1], ah_r[mf], b_r[nf][2], b_r[nf][3]);
            }
    }
}

__device__ __forceinline__ void issue_b(const __nv_bfloat16* __restrict__ bh,
                                        const __nv_bfloat16* __restrict__ bl,
                                        uint32_t base, int kk, int tid) {
#pragma unroll
    for (int i = 0; i < 2; i++) {
        int unit = tid + i * 256;
        int row = unit >> 2, c = unit & 3;
        uint32_t off = row * 64 + ((c ^ (row & 3)) << 4);
        cp16(base + 16384 + off, bh + (size_t)row * 256 + kk * 32 + c * 8, 16);
        cp16(base + 24576 + off, bl + (size_t)row * 256 + kk * 32 + c * 8, 16);
    }
}

__device__ __forceinline__ void gemm_epilogue(
    float (&acc)[2][8][4], const float* __restrict__ bias, float* __restrict__ C,
    float* __restrict__ st, float* smem_stat, int m0, int lane, int wm, int wn,
    int tid) {
#pragma unroll
    for (int nf8 = 0; nf8 < 8; nf8++) {
        int col = wn * 64 + nf8 * 8 + (lane & 3) * 2;
        float bx = __ldg(bias + col);
        float by = __ldg(bias + col + 1);
        float s0 = 0.f, q0 = 0.f, s1 = 0.f, q1 = 0.f;
#pragma unroll
        for (int mf = 0; mf < 2; mf++) {
            float v0 = acc[mf][nf8][0], v1 = acc[mf][nf8][1];
            float v2 = acc[mf][nf8][2], v3 = acc[mf][nf8][3];
            s0 += v0 + v2; q0 += v0 * v0 + v2 * v2;
            s1 += v1 + v3; q1 += v1 * v1 + v3 * v3;
            int r0 = m0 + wm * 32 + mf * 16 + (lane >> 2);
            if (r0 < NN)
                *(float2*)(C + (size_t)r0 * 128 + col) = make_float2(v0 + bx, v1 + by);
            int r1 = r0 + 8;
            if (r1 < NN)
                *(float2*)(C + (size_t)r1 * 128 + col) = make_float2(v2 + bx, v3 + by);
        }
#pragma unroll
        for (int msk = 4; msk < 32; msk <<= 1) {
            s0 += __shfl_xor_sync(0xffffffffu, s0, msk);
            q0 += __shfl_xor_sync(0xffffffffu, q0, msk);
            s1 += __shfl_xor_sync(0xffffffffu, s1, msk);
            q1 += __shfl_xor_sync(0xffffffffu, q1, msk);
        }
        if ((lane >> 2) == 0) {
            atomicAdd(&smem_stat[col], s0);
            atomicAdd(&smem_stat[col + 1], s1);
            atomicAdd(&smem_stat[128 + col], q0);
            atomicAdd(&smem_stat[128 + col + 1], q1);
        }
    }
    __syncthreads();
    if (tid < 256) atomicAdd(st + tid, smem_stat[tid]);
}

// ---------------- GEMM, bf16-split A from g_ah/g_al (3-stage cp.async) ---------
#define GSMEM_STD (3 * STG + 1024)

__device__ __forceinline__ void issue_a_bf(const __nv_bfloat16* __restrict__ ah,
                                           const __nv_bfloat16* __restrict__ al,
                                           uint32_t base, int kk, int m0, int tid) {
#pragma unroll
    for (int i = 0; i < 2; i++) {
        int unit = tid + i * 256;
        int row = unit >> 2, c = unit & 3;
        uint32_t off = row * 64 + ((c ^ (row & 3)) << 4);
        int grow = m0 + row;
        int ok = grow < NN;
        size_t gofs = (size_t)(ok ? grow : 0) * 256 + kk * 32 + c * 8;
        cp16(base + off, ah + gofs, ok ? 16 : 0);
        cp16(base + 8192 + off, al + gofs, ok ? 16 : 0);
    }
}

__global__ void __launch_bounds__(256, 2) gemm_bf(
    const __nv_bfloat16* __restrict__ ah, const __nv_bfloat16* __restrict__ al,
    const __nv_bfloat16* __restrict__ bh, const __nv_bfloat16* __restrict__ bl,
    const float* __restrict__ bias, float* __restrict__ C,
    float* __restrict__ st, int K)
{
    extern __shared__ char smem[];
    const uint32_t sb = s2u(smem);
    float* smem_stat = (float*)(smem + 3 * STG);
    const int tid = threadIdx.x;
    const int lane = tid & 31;
    const int wid = tid >> 5;
    const int wm = wid & 3;
    const int wn = wid >> 2;
    const int m0 = blockIdx.x * 128;
    const int nk = K >> 5;

    if (tid < 256) smem_stat[tid] = 0.f;

    float acc[2][8][4];
#pragma unroll
    for (int i = 0; i < 2; i++)
#pragma unroll
        for (int j = 0; j < 8; j++)
#pragma unroll
            for (int q = 0; q < 4; q++) acc[i][j][q] = 0.f;

    issue_a_bf(ah, al, sb, 0, m0, tid);
    issue_b(bh, bl, sb, 0, tid);
    cp_commit();
    issue_a_bf(ah, al, sb + STG, 1, m0, tid);
    issue_b(bh, bl, sb + STG, 1, tid);
    cp_commit();

    for (int kk = 0; kk < nk; kk++) {
        if (kk < nk - 1) asm volatile("cp.async.wait_group 1;");
        else             asm volatile("cp.async.wait_group 0;");
        __syncthreads();
        if (kk + 2 < nk) {
            uint32_t base = sb + ((kk + 2) % 3) * STG;
            issue_a_bf(ah, al, base, kk + 2, m0, tid);
            issue_b(bh, bl, base, kk + 2, tid);
            cp_commit();
        }
        mma_stage(sb + (kk % 3) * STG, lane, wm, wn, acc);
        __syncthreads();
    }
    gemm_epilogue(acc, bias, C, st, smem_stat, m0, lane, wm, wn, tid);
}

// ---------------- GEMM, fp32 A (in-kernel split, optional fused BN+ReLU) -------
#define GSMEM_F32 (2 * STG + 1024)

template <bool APPLY>
__global__ void __launch_bounds__(256, 2) gemm_f32(
    const float* __restrict__ A,
    const __nv_bfloat16* __restrict__ bh, const __nv_bfloat16* __restrict__ bl,
    const float* __restrict__ bias, float* __restrict__ C,
    float* __restrict__ st, int K)
{
    extern __shared__ char smem[];
    const uint32_t sb = s2u(smem);
    float* smem_stat = (float*)(smem + 2 * STG);
    const int tid = threadIdx.x;
    const int lane = tid & 31;
    const int wid = tid >> 5;
    const int wm = wid & 3;
    const int wn = wid >> 2;
    const int m0 = blockIdx.x * 128;
    const int nk = K >> 5;

    if (tid < 256) smem_stat[tid] = 0.f;

    float acc[2][8][4];
#pragma unroll
    for (int i = 0; i < 2; i++)
#pragma unroll
        for (int j = 0; j < 8; j++)
#pragma unroll
            for (int q = 0; q < 4; q++) acc[i][j][q] = 0.f;

    float4 areg[4];
    // per-thread A mapping: unit = tid + i*256 -> row=unit>>3 (0..127), c=unit&7
    auto ldg_a = [&](int kk) {
#pragma unroll
        for (int i = 0; i < 4; i++) {
            int unit = tid + i * 256;
            int row = unit >> 3, c = unit & 7;
            int grow = m0 + row;
            float4 v = make_float4(0.f, 0.f, 0.f, 0.f);
            if (grow < NN)
                v = __ldg((const float4*)(A + (size_t)grow * K + kk * 32 + c * 4));
            if (APPLY) {
                int ci = kk * 8 + c;
                float4 sc = *((const float4*)g_scale + ci);
                float4 sh = *((const float4*)g_shift + ci);
                v.x = fmaxf(fmaf(v.x, sc.x, sh.x), 0.f);
                v.y = fmaxf(fmaf(v.y, sc.y, sh.y), 0.f);
                v.z = fmaxf(fmaf(v.z, sc.z, sh.z), 0.f);
                v.w = fmaxf(fmaf(v.w, sc.w, sh.w), 0.f);
            }
            areg[i] = v;
        }
    };
    auto sts_a = [&](uint32_t base) {
#pragma unroll
        for (int i = 0; i < 4; i++) {
            int unit = tid + i * 256;
            int row = unit >> 3, c = unit & 7;
            uint2 h, l;
            split4(areg[i], h, l);
            uint32_t off = row * 64 + ((((c >> 1) ^ (row & 3))) << 4) + ((c & 1) << 3);
            *(uint2*)(smem + base - sb + off) = h;            // Ah
            *(uint2*)(smem + base - sb + 8192 + off) = l;     // Al
        }
    };

    ldg_a(0);
    issue_b(bh, bl, sb, 0, tid);
    cp_commit();
    sts_a(sb);
    if (nk > 1) ldg_a(1);

    for (int kk = 0; kk < nk; kk++) {
        asm volatile("cp.async.wait_group 0;");
        __syncthreads();
        uint32_t nbase = sb + ((kk + 1) & 1) * STG;
        if (kk + 1 < nk) {
            issue_b(bh, bl, nbase, kk + 1, tid);
            cp_commit();
            sts_a(nbase);
        }
        if (kk + 2 < nk) ldg_a(kk + 2);
        mma_stage(sb + (kk & 1) * STG, lane, wm, wn, acc);
        __syncthreads();
    }
    gemm_epilogue(acc, bias, C, st, smem_stat, m0, lane, wm, wn, tid);
}

// ---------------- BN finalize + apply -----------------------------------------
__global__ void bn_finalize(const float* __restrict__ st,
                            const float* __restrict__ bias,
                            const float* __restrict__ g,
                            const float* __restrict__ be, float invM) {
    int c = threadIdx.x;
    float mean_raw = st[c] * invM;
    float var = fmaf(-mean_raw, mean_raw, st[128 + c] * invM);
    float mean = mean_raw + bias[c];
    float r = rsqrtf(var + 1e-5f);
    float sc = g[c] * r;
    g_scale[c] = sc;
    g_shift[c] = be[c] - mean * sc;
}

template <bool RELU, bool WF32, bool WBF16>
__global__ void bn_apply(const float4* __restrict__ X, float4* __restrict__ Y,
                         int colofs, int n4) {
    int i = blockIdx.x * blockDim.x + threadIdx.x;
    if (i >= n4) return;
    int gsel = i & 31;
    float4 sc = __ldg((const float4*)g_scale + gsel);
    float4 sh = __ldg((const float4*)g_shift + gsel);
    float4 v = X[i];
    float4 r;
    r.x = fmaf(v.x, sc.x, sh.x);
    r.y = fmaf(v.y, sc.y, sh.y);
    r.z = fmaf(v.z, sc.z, sh.z);
    r.w = fmaf(v.w, sc.w, sh.w);
    if (RELU) {
        r.x = fmaxf(r.x, 0.f);
        r.y = fmaxf(r.y, 0.f);
        r.z = fmaxf(r.z, 0.f);
        r.w = fmaxf(r.w, 0.f);
    }
    if (WF32) Y[i] = r;
    if (WBF16) {
        int row = i >> 5;
        int c = (i & 31) * 4;
        size_t base = (size_t)row * 256 + colofs + c;
        uint2 h, l;
        split4(r, h, l);
        *(uint2*)(g_ah + base) = h;
        *(uint2*)(g_al + base) = l;
    }
}

// ---------------- CSR build -----------------------------------------------------
__global__ void zero_deg() {
    int i = blockIdx.x * blockDim.x + threadIdx.x;
    if (i < NN) g_deg[i] = 0;
}

__global__ void count_deg(const int* __restrict__ dst) {
    for (int e = blockIdx.x * blockDim.x + threadIdx.x; e < EE;
         e += gridDim.x * blockDim.x)
        atomicAdd(&g_deg[__ldg(&dst[e])], 1);
}

__global__ void __launch_bounds__(1024, 1) scan_deg() {
    __shared__ int wsum[32];
    int tid = threadIdx.x, lane = tid & 31, wid = tid >> 5;
    const int CH = (NN + 1023) >> 10;   // 49
    int start = tid * CH;
    int arr[49];
#pragma unroll
    for (int i = 0; i < 49; i++) {
        int idx = start + i;
        arr[i] = (idx < NN) ? g_deg[idx] : 0;
    }
    int s = 0;
#pragma unroll
    for (int i = 0; i < 49; i++) s += arr[i];
    int v = s;
#pragma unroll
    for (int off = 1; off < 32; off <<= 1) {
        int t = __shfl_up_sync(0xffffffffu, v, off);
        if (lane >= off) v += t;
    }
    if (lane == 31) wsum[wid] = v;
    __syncthreads();
    if (wid == 0) {
        int w = wsum[lane];
#pragma unroll
        for (int off = 1; off < 32; off <<= 1) {
            int t = __shfl_up_sync(0xffffffffu, w, off);
            if (lane >= off) w += t;
        }
        wsum[lane] = w;
    }
    __syncthreads();
    int run = (wid ? wsum[wid - 1] : 0) + (v - s);
#pragma unroll
    for (int i = 0; i < 49; i++) {
        int idx = start + i;
        if (idx < NN) {
            g_rowptr[idx] = run;
            g_pos[idx] = run;
            run += arr[i];
        }
    }
    if (tid == 1023) g_rowptr[NN] = run;
}

__global__ void fill_csr(const int* __restrict__ src, const int* __restrict__ dst) {
    for (int e = blockIdx.x * blockDim.x + threadIdx.x; e < EE;
         e += gridDim.x * blockDim.x) {
        int d = __ldg(&dst[e]);
        int p = atomicAdd(&g_pos[d], 1);
        g_col[p] = __ldg(&src[e]);
    }
}

// ---------------- SAGE mean aggregation from bf16-hi, split output ------------
__global__ void sage_agg_h(int in_ofs) {
    int gw = (blockIdx.x * blockDim.x + threadIdx.x) >> 5;
    int lane = threadIdx.x & 31;
    if (gw >= NN) return;
    int beg = g_rowptr[gw], end = g_rowptr[gw + 1];
    float a0 = 0.f, a1 = 0.f, a2 = 0.f, a3 = 0.f;
#pragma unroll 4
    for (int e = beg; e < end; e++) {
        int s = __ldg(&g_col[e]);
        uint2 v = __ldg((const uint2*)(g_ah + (size_t)s * 256 + in_ofs + lane * 4));
        a0 += __uint_as_float(v.x << 16);
        a1 += __uint_as_float(v.x & 0xffff0000u);
        a2 += __uint_as_float(v.y << 16);
        a3 += __uint_as_float(v.y & 0xffff0000u);
    }
    int d = end - beg;
    float inv = 1.0f / (float)(d > 0 ? d : 1);
    float4 acc = make_float4(a0 * inv, a1 * inv, a2 * inv, a3 * inv);
    uint2 h, l;
    split4(acc, h, l);
    size_t base = (size_t)gw * 256 + lane * 4;
    *(uint2*)(g_ah + base) = h;
    *(uint2*)(g_al + base) = l;
}

// ---------------- launch ---------------------------------------------------------
extern "C" void kernel_launch(void* const* d_in, const int* in_sizes, int n_in,
                              void* d_out, int out_size) {
    const float* x     = (const float*)d_in[0];
    const int*   ei    = (const int*)d_in[1];
    const float* W_in  = (const float*)d_in[2];
    const float* b_in  = (const float*)d_in[3];
    const float* g1    = (const float*)d_in[4];
    const float* be1   = (const float*)d_in[5];
    const float* W_hid = (const float*)d_in[6];
    const float* b_hid = (const float*)d_in[7];
    const float* g2    = (const float*)d_in[8];
    const float* be2   = (const float*)d_in[9];
    const float* Wl1   = (const float*)d_in[10];
    const float* bl1   = (const float*)d_in[11];
    const float* Wr1   = (const float*)d_in[12];
    const float* g3    = (const float*)d_in[13];
    const float* be3   = (const float*)d_in[14];
    const float* Wl2   = (const float*)d_in[15];
    const float* bl2   = (const float*)d_in[16];
    const float* Wr2   = (const float*)d_in[17];
    const float* g4    = (const float*)d_in[18];
    const float* be4   = (const float*)d_in[19];

    const int* src = ei;
    const int* dst = ei + EE;
    float* out_feat = (float*)d_out;
    float* out_out  = out_feat + (size_t)NN * 128;

    void *p0, *p1, *pah, *pal, *pbh, *pbl, *pst;
    cudaGetSymbolAddress(&p0, g_b0);
    cudaGetSymbolAddress(&p1, g_b1);
    cudaGetSymbolAddress(&pah, g_ah);
    cudaGetSymbolAddress(&pal, g_al);
    cudaGetSymbolAddress(&pbh, g_bwh);
    cudaGetSymbolAddress(&pbl, g_bwl);
    cudaGetSymbolAddress(&pst, g_stats);
    float* b0 = (float*)p0;
    float* b1 = (float*)p1;
    __nv_bfloat16* ah = (__nv_bfloat16*)pah;
    __nv_bfloat16* al = (__nv_bfloat16*)pal;
    __nv_bfloat16* bwh = (__nv_bfloat16*)pbh;
    __nv_bfloat16* bwl = (__nv_bfloat16*)pbl;
    float* st = (float*)pst;

    static cudaStream_t s_csr = nullptr;
    static cudaEvent_t ev_fork = nullptr, ev_csr = nullptr;
    static bool setup_done = false;
    if (!setup_done) {
        cudaFuncSetAttribute(gemm_bf, cudaFuncAttributeMaxDynamicSharedMemorySize,
                             GSMEM_STD);
        cudaFuncSetAttribute(gemm_f32<false>,
                             cudaFuncAttributeMaxDynamicSharedMemorySize, GSMEM_F32);
        cudaFuncSetAttribute(gemm_f32<true>,
                             cudaFuncAttributeMaxDynamicSharedMemorySize, GSMEM_F32);
        cudaStreamCreateWithFlags(&s_csr, cudaStreamNonBlocking);
        cudaEventCreateWithFlags(&ev_fork, cudaEventDisableTiming);
        cudaEventCreateWithFlags(&ev_csr, cudaEventDisableTiming);
        setup_done = true;
    }

    const int n4 = NN * 32;
    const int gBN = (n4 + 255) / 256;
    const float invM = 1.0f / (float)NN;

    // ---- fork: CSR build on side stream ----
    cudaEventRecord(ev_fork, 0);
    cudaStreamWaitEvent(s_csr, ev_fork, 0);
    zero_deg<<<(NN + 255) / 256, 256, 0, s_csr>>>();
    count_deg<<<4096, 256, 0, s_csr>>>(dst);
    scan_deg<<<1, 1024, 0, s_csr>>>();
    fill_csr<<<4096, 256, 0, s_csr>>>(src, dst);
    cudaEventRecord(ev_csr, s_csr);

    // ---- main stream ----
    zero_stats<<<1, 1024>>>();
    prep_w<<<512, 256>>>(W_in, W_hid, Wl1, Wr1, Wl2, Wr2);

    // layer 1: h1 = x @ W_in + b_in (fp32 A direct; BN stats fused)
    gemm_f32<false><<<MTILES, 256, GSMEM_F32>>>(x, bwh, bwl, b_in, b0, st, 256);
    bn_finalize<<<1, 128>>>(st, b_in, g1, be1, invM);

    // layer 2: feat = relu(BN1) fused into A-load; output b1 + fp32/bf16 via bn_apply
    gemm_f32<true><<<MTILES, 256, GSMEM_F32>>>(b0, bwh + 32768, bwl + 32768, b_hid,
                                               b1, st + 256, 128);
    bn_finalize<<<1, 128>>>(st + 256, b_hid, g2, be2, invM);
    bn_apply<true, true, true><<<gBN, 256>>>((const float4*)b1, (float4*)out_feat,
                                             128, n4);

    // ---- join CSR before first aggregation ----
    cudaStreamWaitEvent(0, ev_csr, 0);

    // SAGE 1
    sage_agg_h<<<(NN * 32 + 255) / 256, 256>>>(128);
    gemm_bf<<<MTILES, 256, GSMEM_STD>>>(ah, al, bwh + 2 * 32768, bwl + 2 * 32768,
                                        bl1, b0, st + 512, 256);
    bn_finalize<<<1, 128>>>(st + 512, bl1, g3, be3, invM);
    bn_apply<false, false, true><<<gBN, 256>>>((const float4*)b0, nullptr, 128, n4);

    // SAGE 2
    sage_agg_h<<<(NN * 32 + 255) / 256, 256>>>(128);
    gemm_bf<<<MTILES, 256, GSMEM_STD>>>(ah, al, bwh + 3 * 32768, bwl + 3 * 32768,
                                        bl2, b1, st + 768, 256);
    bn_finalize<<<1, 128>>>(st + 768, bl2, g4, be4, invM);
    bn_apply<false, true, false><<<gBN, 256>>>((const float4*)b1, (float4*)out_out,
                                               0, n4);
}